// round 11
// baseline (speedup 1.0000x reference)
#include <cuda_runtime.h>
#include <cuda_bf16.h>

// ---------------------------------------------------------------------------
// FrameAveraging: center/covariance -> 3x3 eigh (LAPACK ssyevd emulation for
// exact sign/order match with jnp.linalg.eigh) -> 8-way sign-flipped
// frame projection.
//
// Outputs (concatenated in d_out): h [B*8,N,3], F_ops [B,8,3,3], center [B,3]
//
// R11 changes vs R10 (33.06us):
//  - reduce: COALESCED X loads (lane-contiguous float4, 4 sectors/LDG instead
//    of 12 for the 48B-stride pattern). Component phases handled by the
//    slot/discard trick: per-element compile-time slot (2c+e)%3, invalid
//    cross-point products land in slots discarded at the final lane-phase
//    un-permutation. Point-straddling products via shfl_down. Masked sums
//    pair each element with one of two scalar mask loads.
//  - eig, project: unchanged from R10 (passing).
// ---------------------------------------------------------------------------

#define FA_MAXB 1024
__device__ double g_acc[FA_MAXB * 11];   // zero-initialized; restored to 0 each launch
__device__ float g_center[FA_MAXB * 3];
__device__ float g_V[FA_MAXB * 9];       // V[i][j] row-major (column j = eigvec j)

// ----------------------------- LAPACK helpers ------------------------------

__device__ __forceinline__ float f_sign(float a, float b) {
    float aa = fabsf(a);
    return (b >= 0.0f) ? aa : -aa;
}

__device__ __forceinline__ float slapy2f(float x, float y) {
    float ax = fabsf(x), ay = fabsf(y);
    float w = fmaxf(ax, ay), z = fminf(ax, ay);
    if (z == 0.0f) return w;
    float r = z / w;
    return w * sqrtf(1.0f + r * r);
}

// LAPACK >= 3.10 slartg convention: c >= 0, r = sign(f)*hypot, s = g/r.
__device__ __forceinline__ void slartgf(float f, float g, float& c, float& s, float& r) {
    if (g == 0.0f) {
        c = 1.0f; s = 0.0f; r = f;
    } else if (f == 0.0f) {
        c = 0.0f; s = (g >= 0.0f) ? 1.0f : -1.0f; r = fabsf(g);
    } else {
        float d = sqrtf(f * f + g * g);
        c = fabsf(f) / d;
        r = (f >= 0.0f) ? d : -d;
        s = g / r;
    }
}

__device__ void slaev2f(float a, float b, float c,
                        float& rt1, float& rt2, float& cs1, float& sn1) {
    float sm = a + c;
    float df = a - c;
    float adf = fabsf(df);
    float tb = b + b;
    float ab = fabsf(tb);
    float acmx, acmn;
    if (fabsf(a) > fabsf(c)) { acmx = a; acmn = c; } else { acmx = c; acmn = a; }
    float rt;
    if (adf > ab)      { float q = ab / adf;  rt = adf * sqrtf(1.0f + q * q); }
    else if (adf < ab) { float q = adf / ab;  rt = ab  * sqrtf(1.0f + q * q); }
    else               {                      rt = ab  * sqrtf(2.0f); }
    int sgn1;
    if (sm < 0.0f) {
        rt1 = 0.5f * (sm - rt); sgn1 = -1;
        rt2 = (acmx / rt1) * acmn - (b / rt1) * b;
    } else if (sm > 0.0f) {
        rt1 = 0.5f * (sm + rt); sgn1 = 1;
        rt2 = (acmx / rt1) * acmn - (b / rt1) * b;
    } else {
        rt1 = 0.5f * rt; rt2 = -0.5f * rt; sgn1 = 1;
    }
    float cs; int sgn2;
    if (df >= 0.0f) { cs = df + rt; sgn2 = 1; } else { cs = df - rt; sgn2 = -1; }
    float acs = fabsf(cs);
    if (acs > ab) {
        float ct = -tb / cs;
        sn1 = 1.0f / sqrtf(1.0f + ct * ct);
        cs1 = ct * sn1;
    } else {
        if (ab == 0.0f) { cs1 = 1.0f; sn1 = 0.0f; }
        else {
            float tn = -cs / tb;
            cs1 = 1.0f / sqrtf(1.0f + tn * tn);
            sn1 = tn * cs1;
        }
    }
    if (sgn1 == sgn2) { float tn = cs1; cs1 = -sn1; sn1 = tn; }
}

// ssteqr, COMPZ='I', n=3. d[3], e[2], z initialized to identity by the caller.
__device__ void ssteqr3(float d[3], float e[2], float z[3][3]) {
    const float eps = 5.9604645e-08f;          // slamch('E') for f32 = 2^-24
    const float eps2 = eps * eps;
    const float safmin = 1.1754943508222875e-38f;
    const int n = 3;
    const int nmaxit = n * 30;
    int jtot = 0;
    int l1 = 0;

    while (true) {
        if (l1 > n - 1) break;
        if (l1 > 0) e[l1 - 1] = 0.0f;
        int m = n - 1;
        for (int mm = l1; mm <= n - 2; mm++) {
            float tst = fabsf(e[mm]);
            if (tst == 0.0f) { m = mm; break; }
            if (tst <= (sqrtf(fabsf(d[mm])) * sqrtf(fabsf(d[mm + 1]))) * eps) {
                e[mm] = 0.0f; m = mm; break;
            }
        }
        int l = l1, lsv = l, lend = m, lendsv = lend;
        l1 = m + 1;
        if (lend == l) continue;
        if (fabsf(d[lend]) < fabsf(d[l])) { l = lendsv; lend = lsv; }

        if (lend > l) {
            // ---- QL iteration ----
            bool blockdone = false;
            while (!blockdone) {
                int m2 = lend;
                if (l != lend) {
                    for (int mm = l; mm <= lend - 1; mm++) {
                        float tst = e[mm] * e[mm];
                        if (tst <= (eps2 * fabsf(d[mm])) * fabsf(d[mm + 1]) + safmin) {
                            m2 = mm; break;
                        }
                    }
                }
                if (m2 < lend) e[m2] = 0.0f;
                float p = d[l];
                if (m2 == l) {
                    d[l] = p; l++;
                    if (l <= lend) continue;
                    blockdone = true; continue;
                }
                if (m2 == l + 1) {
                    float rt1, rt2, c, s;
                    slaev2f(d[l], e[l], d[l + 1], rt1, rt2, c, s);
                    for (int i = 0; i < 3; i++) {
                        float temp = z[i][l + 1];
                        z[i][l + 1] = c * temp - s * z[i][l];
                        z[i][l]     = s * temp + c * z[i][l];
                    }
                    d[l] = rt1; d[l + 1] = rt2; e[l] = 0.0f;
                    l += 2;
                    if (l <= lend) continue;
                    blockdone = true; continue;
                }
                if (jtot == nmaxit) { blockdone = true; continue; }
                jtot++;
                float g = (d[l + 1] - p) / (2.0f * e[l]);
                float r = slapy2f(g, 1.0f);
                g = d[m2] - p + e[l] / (g + f_sign(r, g));
                float s = 1.0f, c = 1.0f;
                p = 0.0f;
                float csv[2], snv[2];
                for (int i = m2 - 1; i >= l; i--) {
                    float f = s * e[i];
                    float b2 = c * e[i];
                    slartgf(g, f, c, s, r);
                    if (i != m2 - 1) e[i + 1] = r;
                    g = d[i + 1] - p;
                    r = (d[i] - g) * s + 2.0f * c * b2;
                    p = s * r;
                    d[i + 1] = g + p;
                    g = c * r - b2;
                    csv[i] = c; snv[i] = -s;
                }
                for (int j = m2 - 1; j >= l; j--) {        // slasr 'R','V','B'
                    float cj = csv[j], sj = snv[j];
                    for (int i = 0; i < 3; i++) {
                        float temp = z[i][j + 1];
                        z[i][j + 1] = cj * temp - sj * z[i][j];
                        z[i][j]     = sj * temp + cj * z[i][j];
                    }
                }
                d[l] = d[l] - p;
                e[l] = g;
            }
        } else {
            // ---- QR iteration ----
            bool blockdone = false;
            while (!blockdone) {
                int m2 = lend;
                if (l != lend) {
                    for (int mm = l; mm >= lend + 1; mm--) {
                        float tst = e[mm - 1] * e[mm - 1];
                        if (tst <= (eps2 * fabsf(d[mm])) * fabsf(d[mm - 1]) + safmin) {
                            m2 = mm; break;
                        }
                    }
                }
                if (m2 > lend) e[m2 - 1] = 0.0f;
                float p = d[l];
                if (m2 == l) {
                    d[l] = p; l--;
                    if (l >= lend) continue;
                    blockdone = true; continue;
                }
                if (m2 == l - 1) {
                    float rt1, rt2, c, s;
                    slaev2f(d[l - 1], e[l - 1], d[l], rt1, rt2, c, s);
                    for (int i = 0; i < 3; i++) {
                        float temp = z[i][l];
                        z[i][l]     = c * temp - s * z[i][l - 1];
                        z[i][l - 1] = s * temp + c * z[i][l - 1];
                    }
                    d[l - 1] = rt1; d[l] = rt2; e[l - 1] = 0.0f;
                    l -= 2;
                    if (l >= lend) continue;
                    blockdone = true; continue;
                }
                if (jtot == nmaxit) { blockdone = true; continue; }
                jtot++;
                float g = (d[l - 1] - p) / (2.0f * e[l - 1]);
                float r = slapy2f(g, 1.0f);
                g = d[m2] - p + e[l - 1] / (g + f_sign(r, g));
                float s = 1.0f, c = 1.0f;
                p = 0.0f;
                float csv[2], snv[2];
                for (int i = m2; i <= l - 1; i++) {
                    float f = s * e[i];
                    float b2 = c * e[i];
                    slartgf(g, f, c, s, r);
                    if (i != m2) e[i - 1] = r;
                    g = d[i] - p;
                    r = (d[i + 1] - g) * s + 2.0f * c * b2;
                    p = s * r;
                    d[i] = g + p;
                    g = c * r - b2;
                    csv[i] = c; snv[i] = s;
                }
                for (int j = m2; j <= l - 1; j++) {        // slasr 'R','V','F'
                    float cj = csv[j], sj = snv[j];
                    for (int i = 0; i < 3; i++) {
                        float temp = z[i][j + 1];
                        z[i][j + 1] = cj * temp - sj * z[i][j];
                        z[i][j]     = sj * temp + cj * z[i][j];
                    }
                }
                d[l] = d[l] - p;
                e[l - 1] = g;
            }
        }
    }
    // Selection sort ascending, swapping eigenvector columns (LAPACK label 160).
    for (int ii = 1; ii < n; ii++) {
        int i = ii - 1, k = i;
        float p = d[i];
        for (int j = ii; j < n; j++) if (d[j] < p) { k = j; p = d[j]; }
        if (k != i) {
            d[k] = d[i]; d[i] = p;
            for (int r2 = 0; r2 < 3; r2++) {
                float t = z[r2][i]; z[r2][i] = z[r2][k]; z[r2][k] = t;
            }
        }
    }
}

// ----------------------------- Kernel 1: reduce ----------------------------
// grid (ceil(N/1024), B), block 256. Each warp owns 384 contiguous floats
// (=128 points). Lane-contiguous float4 X loads (minimal sectors); component
// phases via the slot/discard trick; straddling products via shfl_down;
// masked sums via two scalar mask loads per chunk.

__device__ __forceinline__ float warpRedF(float v) {
#pragma unroll
    for (int o = 16; o > 0; o >>= 1) v += __shfl_down_sync(0xffffffffu, v, o);
    return v;
}

__device__ __forceinline__ float sel3(const float a[3], int t) {
    return (t == 0) ? a[0] : ((t == 1) ? a[1] : a[2]);
}

__global__ void __launch_bounds__(256)
fa_reduce_kernel(const float* __restrict__ X,
                 const float* __restrict__ mask, int N) {
    const unsigned FULL = 0xffffffffu;
    int b = blockIdx.y;
    const float4* Xrow4 = reinterpret_cast<const float4*>(X + (size_t)b * N * 3);
    const float* Mrow = mask + (size_t)b * N;

    int tid = threadIdx.x;
    int lane = tid & 31, w = tid >> 5;
    int nf4 = (N * 3) >> 2;                 // float4 count per row
    int Wf = blockIdx.x * 3072 + w * 384;   // warp region first float (div by 3)
    int Wf4 = Wf >> 2;
    int Wp = Wf / 3;                        // warp region first point

    float4 f4[3];
    float mAv[3], mBv[3];
    int rr[3];
#pragma unroll
    for (int c = 0; c < 3; c++) {
        int q4 = Wf4 + 32 * c + lane;
        f4[c] = (q4 < nf4) ? Xrow4[q4] : make_float4(0.f, 0.f, 0.f, 0.f);
        int jl = 128 * c + 4 * lane;        // local float offset of element 0
        int pl = jl / 3;
        rr[c] = jl - pl * 3;                // jl mod 3
        int pg = Wp + pl;
        mAv[c] = (pg < N) ? Mrow[pg] : 0.f;
        mBv[c] = (pg + 1 < N) ? Mrow[pg + 1] : 0.f;
    }

    // slot accumulators (slot = (2c+e) % 3; real phase = (lane%3 + slot) % 3)
    float sq[3]   = {0.f, 0.f, 0.f};   // f^2            -> xx/yy/zz by phase
    float p1a[3]  = {0.f, 0.f, 0.f};   // f_j*f_{j+1}    -> xy(ph0)/yz(ph1); ph2 discarded
    float p2a[3]  = {0.f, 0.f, 0.f};   // f_j*f_{j+2}    -> xz(ph0); ph1/ph2 discarded
    float mfa[3]  = {0.f, 0.f, 0.f};   // m*f            -> s1x/s1y/s1z by phase
    float mma[3]  = {0.f, 0.f, 0.f};   // m              -> Sm (ph0 only)
    float mm2a[3] = {0.f, 0.f, 0.f};   // m^2            -> Sm2 (ph0 only)

#pragma unroll
    for (int c = 0; c < 3; c++) {
        float v0 = f4[c].x, v1 = f4[c].y, v2 = f4[c].z, v3 = f4[c].w;
        float n0 = __shfl_down_sync(FULL, v0, 1);
        float n1 = __shfl_down_sync(FULL, v1, 1);
        if (c < 2) {
            float bx = __shfl_sync(FULL, f4[c + 1].x, 0);
            float by = __shfl_sync(FULL, f4[c + 1].y, 0);
            if (lane == 31) { n0 = bx; n1 = by; }
        } else {
            if (lane == 31) { n0 = 0.f; n1 = 0.f; }   // discarded slots anyway
        }
        int r = rr[c];
        float mA = mAv[c], mB = mBv[c];
        float m0 = mA;                       // e=0: r+0 < 3 always
        float m1 = (r < 2) ? mA : mB;
        float m2 = (r < 1) ? mA : mB;
        float m3 = mB;                       // e=3: r+3 >= 3 always
        const int s0 = (2 * c + 0) % 3;
        const int s1 = (2 * c + 1) % 3;
        const int s2 = (2 * c + 2) % 3;
        const int s3 = s0;                   // (2c+3) % 3

        sq[s0] = fmaf(v0, v0, sq[s0]);
        sq[s1] = fmaf(v1, v1, sq[s1]);
        sq[s2] = fmaf(v2, v2, sq[s2]);
        sq[s3] = fmaf(v3, v3, sq[s3]);

        p1a[s0] = fmaf(v0, v1, p1a[s0]);
        p1a[s1] = fmaf(v1, v2, p1a[s1]);
        p1a[s2] = fmaf(v2, v3, p1a[s2]);
        p1a[s3] = fmaf(v3, n0, p1a[s3]);

        p2a[s0] = fmaf(v0, v2, p2a[s0]);
        p2a[s1] = fmaf(v1, v3, p2a[s1]);
        p2a[s2] = fmaf(v2, n0, p2a[s2]);
        p2a[s3] = fmaf(v3, n1, p2a[s3]);

        mfa[s0] = fmaf(m0, v0, mfa[s0]);
        mfa[s1] = fmaf(m1, v1, mfa[s1]);
        mfa[s2] = fmaf(m2, v2, mfa[s2]);
        mfa[s3] = fmaf(m3, v3, mfa[s3]);

        mma[s0] += m0; mma[s1] += m1; mma[s2] += m2; mma[s3] += m3;
        mm2a[s0] = fmaf(m0, m0, mm2a[s0]);
        mm2a[s1] = fmaf(m1, m1, mm2a[s1]);
        mm2a[s2] = fmaf(m2, m2, mm2a[s2]);
        mm2a[s3] = fmaf(m3, m3, mm2a[s3]);
    }

    // un-permute: slot holding real phase p is (p - lane%3) mod 3
    int lam = lane % 3;
    int t0 = (3 - lam) % 3;
    int t1 = (4 - lam) % 3;
    int t2 = (5 - lam) % 3;
    float acc[11];
    acc[0]  = sel3(mma,  t0);   // Sm
    acc[1]  = sel3(mm2a, t0);   // Sm2
    acc[2]  = sel3(mfa,  t0);   // s1x
    acc[3]  = sel3(mfa,  t1);   // s1y
    acc[4]  = sel3(mfa,  t2);   // s1z
    acc[5]  = sel3(sq,   t0);   // xx
    acc[6]  = sel3(p1a,  t0);   // xy
    acc[7]  = sel3(p2a,  t0);   // xz
    acc[8]  = sel3(sq,   t1);   // yy
    acc[9]  = sel3(p1a,  t1);   // yz
    acc[10] = sel3(sq,   t2);   // zz

    __shared__ float sred[8][11];
#pragma unroll
    for (int k = 0; k < 11; k++) {
        float v = warpRedF(acc[k]);
        if (lane == 0) sred[w][k] = v;
    }
    __syncthreads();
    if (tid < 11) {
        double v = 0.0;
#pragma unroll
        for (int ww = 0; ww < 8; ww++) v += (double)sred[ww][tid];
        atomicAdd(&g_acc[b * 11 + tid], v);
    }
}

// ------------------- Kernel 2: finalize + eigh + F_ops ----------------------
// One matrix per CTA (lane 0 only) -> no warp divergence in ssteqr emulation.

__global__ void __launch_bounds__(32)
fa_eig_kernel(float* __restrict__ outF, float* __restrict__ outC, int B) {
    int b = blockIdx.x;
    if (threadIdx.x != 0 || b >= B) return;

    double t[11];
#pragma unroll
    for (int k = 0; k < 11; k++) {
        t[k] = g_acc[b * 11 + k];
        g_acc[b * 11 + k] = 0.0;      // restore zero state for next launch
    }
    double sm = t[0], sm2 = t[1];
    double s1x = t[2], s1y = t[3], s1z = t[4];
    // f32 center exactly as reference computes (f32 divide)
    float cfx = (float)s1x / (float)sm;
    float cfy = (float)s1y / (float)sm;
    float cfz = (float)s1z / (float)sm;
    g_center[b * 3 + 0] = cfx;
    g_center[b * 3 + 1] = cfy;
    g_center[b * 3 + 2] = cfz;
    // C_ij = Sxx_ij - c_i*S1_j - c_j*S1_i + c_i*c_j*Sm2 (double expansion)
    double cx = s1x / sm, cy = s1y / sm, cz = s1z / sm;
    float a11 = (float)(t[5]  - 2.0 * cx * s1x + cx * cx * sm2);
    float a21 = (float)(t[6]  - cx * s1y - cy * s1x + cx * cy * sm2);
    float a31 = (float)(t[7]  - cx * s1z - cz * s1x + cx * cz * sm2);
    float a22 = (float)(t[8]  - 2.0 * cy * s1y + cy * cy * sm2);
    float a32 = (float)(t[9]  - cy * s1z - cz * s1y + cy * cz * sm2);
    float a33 = (float)(t[10] - 2.0 * cz * s1z + cz * cz * sm2);

    // ---- ssytd2 (lower, n=3): one Householder reflector ----
    float d[3], e[2];
    float tau = 0.0f, v2 = 0.0f;
    {
        float alpha = a21;
        float xnorm = fabsf(a31);
        if (xnorm == 0.0f) {
            tau = 0.0f; v2 = 0.0f;
            e[0] = alpha;
            d[0] = a11; d[1] = a22; d[2] = a33;
            e[1] = a32;
        } else {
            float beta = -f_sign(slapy2f(alpha, xnorm), alpha);
            tau = (beta - alpha) / beta;
            v2 = a31 * (1.0f / (alpha - beta));
            e[0] = beta;
            float w1 = tau * (a22 + a32 * v2);
            float w2 = tau * (a32 + a33 * v2);
            float alpha2 = -0.5f * tau * (w1 + w2 * v2);
            w1 += alpha2;
            w2 += alpha2 * v2;
            d[0] = a11;
            d[1] = a22 - 2.0f * w1;
            e[1] = a32 - (v2 * w1 + w2);
            d[2] = a33 - 2.0f * v2 * w2;
        }
    }

    float z[3][3] = {{1.f, 0.f, 0.f}, {0.f, 1.f, 0.f}, {0.f, 0.f, 1.f}};
    ssteqr3(d, e, z);

    // ---- sormtr: V = H1 * Z, H1 = I - tau*u*u^T, u = (0, 1, v2) ----
    float V[3][3];
#pragma unroll
    for (int j = 0; j < 3; j++) {
        float tt = tau * (z[1][j] + v2 * z[2][j]);
        V[0][j] = z[0][j];
        V[1][j] = z[1][j] - tt;
        V[2][j] = z[2][j] - v2 * tt;
    }
#pragma unroll
    for (int i = 0; i < 3; i++)
#pragma unroll
        for (int j = 0; j < 3; j++)
            g_V[b * 9 + i * 3 + j] = V[i][j];

    // F_ops[b,o,i,j] = OPS[o][j] * V[i][j]; OPS[o] = (o&4?+1:-1, o&2?+1:-1, o&1?+1:-1)
    for (int o = 0; o < 8; o++) {
        float sg[3] = {(o & 4) ? 1.f : -1.f, (o & 2) ? 1.f : -1.f, (o & 1) ? 1.f : -1.f};
#pragma unroll
        for (int i = 0; i < 3; i++)
#pragma unroll
            for (int j = 0; j < 3; j++)
                outF[(((size_t)b * 8 + o) * 3 + i) * 3 + j] = sg[j] * V[i][j];
    }
    outC[b * 3 + 0] = cfx;
    outC[b * 3 + 1] = cfy;
    outC[b * 3 + 2] = cfz;
}

// ------------------------- Kernel 3: projection (h) -------------------------
// Block = 256 threads = 1024-point tile. Stage y in smem, then write each op
// row with lane-contiguous float4 stores; signs applied by XOR of sign bit.

__global__ void __launch_bounds__(256)
fa_project_kernel(const float* __restrict__ X,
                  const float* __restrict__ mask,
                  float* __restrict__ outh, int N) {
    int b = blockIdx.y;
    __shared__ float4 sy4[768];          // 1024 points * 3 floats = 3072 f = 768 f4
    __shared__ float sV[9];
    __shared__ float sc[3];
    if (threadIdx.x < 9) sV[threadIdx.x] = g_V[b * 9 + threadIdx.x];
    if (threadIdx.x < 3) sc[threadIdx.x] = g_center[b * 3 + threadIdx.x];
    __syncthreads();

    int tid = threadIdx.x;
    int nq = N >> 2;                      // float4-groups per batch row
    int g = blockIdx.x * blockDim.x + tid;  // this thread's group (4 points)
    bool valid = g < nq;

    const float4* Xb = reinterpret_cast<const float4*>(X + (size_t)b * N * 3);
    const float4* Mb = reinterpret_cast<const float4*>(mask + (size_t)b * N);

    if (valid) {
        float4 fa = Xb[g * 3 + 0];
        float4 fb = Xb[g * 3 + 1];
        float4 fc = Xb[g * 3 + 2];
        float4 m4 = Mb[g];

        float cx = sc[0], cy = sc[1], cz = sc[2];
        float v0 = sV[0], v1 = sV[1], v2 = sV[2];
        float v3 = sV[3], v4 = sV[4], v5 = sV[5];
        float v6 = sV[6], v7 = sV[7], v8 = sV[8];

        float px[4] = {fa.x, fa.w, fb.z, fc.y};
        float py[4] = {fa.y, fb.x, fb.w, fc.z};
        float pz[4] = {fa.z, fb.y, fc.x, fc.w};
        float mm[4] = {m4.x, m4.y, m4.z, m4.w};

        float yv[12];
#pragma unroll
        for (int k = 0; k < 4; k++) {
            float xcx = px[k] - cx * mm[k];
            float xcy = py[k] - cy * mm[k];
            float xcz = pz[k] - cz * mm[k];
            // y_i = sum_j V[j][i] * xc_j (projection onto eigenvector i)
            yv[k * 3 + 0] = v0 * xcx + v3 * xcy + v6 * xcz;
            yv[k * 3 + 1] = v1 * xcx + v4 * xcy + v7 * xcz;
            yv[k * 3 + 2] = v2 * xcx + v5 * xcy + v8 * xcz;
        }
        sy4[tid * 3 + 0] = make_float4(yv[0], yv[1], yv[2],  yv[3]);
        sy4[tid * 3 + 1] = make_float4(yv[4], yv[5], yv[6],  yv[7]);
        sy4[tid * 3 + 2] = make_float4(yv[8], yv[9], yv[10], yv[11]);
    }
    __syncthreads();

    // Tile covers points [tile0, tile0 + 1024); floats [tile0*3, +3072).
    int tile0 = blockIdx.x * blockDim.x * 4;           // first point of tile
    int tile_pts = min(N - tile0, (int)blockDim.x * 4);
    int tile_f4 = (tile_pts * 3) >> 2;                 // float4 count in tile

    // Read this thread's 3 unsigned float4s once; reuse across all 8 ops.
    // Precompute idx%3 per chunk (idx = tid + c*256; 256 % 3 == 1 -> m rotates).
    uint4 u[3];
    int mmod[3];
    int mt = tid % 3;
#pragma unroll
    for (int c = 0; c < 3; c++) {
        int idx = tid + c * 256;
        mmod[c] = mt;
        mt = (mt == 2) ? 0 : mt + 1;     // (tid + 256) % 3 advances by 1
        if (idx < tile_f4) {
            float4 v = sy4[idx];
            u[c] = make_uint4(__float_as_uint(v.x), __float_as_uint(v.y),
                              __float_as_uint(v.z), __float_as_uint(v.w));
        }
    }

    size_t rowstride = (size_t)N * 3;
    float* obase = outh + ((size_t)b * 8) * rowstride + (size_t)tile0 * 3;

#pragma unroll
    for (int o = 0; o < 8; o++) {
        // component sign masks: +1 -> 0, -1 -> 0x80000000
        unsigned s0 = (o & 4) ? 0u : 0x80000000u;
        unsigned s1 = (o & 2) ? 0u : 0x80000000u;
        unsigned s2 = (o & 1) ? 0u : 0x80000000u;
        // sign-vector for a float4 starting at float offset f (by f mod 3)
        uint4 sm0 = make_uint4(s0, s1, s2, s0);
        uint4 sm1 = make_uint4(s1, s2, s0, s1);
        uint4 sm2 = make_uint4(s2, s0, s1, s2);
        uint4* orow = reinterpret_cast<uint4*>(obase + (size_t)o * rowstride);
#pragma unroll
        for (int c = 0; c < 3; c++) {
            int idx = tid + c * 256;
            if (idx < tile_f4) {
                int m = mmod[c];
                uint4 sv = (m == 0) ? sm0 : (m == 1) ? sm1 : sm2;
                uint4 w = make_uint4(u[c].x ^ sv.x, u[c].y ^ sv.y,
                                     u[c].z ^ sv.z, u[c].w ^ sv.w);
                __stcs(orow + idx, w);
            }
        }
    }
}

// ------------------------------- launch ------------------------------------

extern "C" void kernel_launch(void* const* d_in, const int* in_sizes, int n_in,
                              void* d_out, int out_size) {
    const float* X = (const float*)d_in[0];
    const float* mask = (const float*)d_in[1];
    float* out = (float*)d_out;

    long long BN = in_sizes[1];                       // B*N
    long long B = ((long long)out_size - 24LL * BN) / 75LL;
    if (B < 1) B = 1;
    int N = (int)(BN / B);

    float* outF = out + 24LL * BN;                    // F_ops after h
    float* outC = outF + 72LL * B;                    // center after F_ops

    int Sr = (N + 1023) / 1024;                       // 1024 points per CTA
    if (Sr < 1) Sr = 1;
    dim3 rgrid((unsigned)Sr, (unsigned)B);
    fa_reduce_kernel<<<rgrid, 256>>>(X, mask, N);
    fa_eig_kernel<<<(int)B, 32>>>(outF, outC, (int)B);
    int nq = N / 4;
    dim3 pgrid((unsigned)((nq + 255) / 256), (unsigned)B);
    fa_project_kernel<<<pgrid, 256>>>(X, mask, out, N);
}

// round 13
// speedup vs baseline: 1.0517x; 1.0517x over previous
#include <cuda_runtime.h>
#include <cuda_bf16.h>
#include <cstdint>

// ---------------------------------------------------------------------------
// FrameAveraging: center/covariance -> 3x3 eigh (LAPACK ssyevd emulation for
// exact sign/order match with jnp.linalg.eigh) -> 8-way sign-flipped
// frame projection.
//
// Outputs (concatenated in d_out): h [B*8,N,3], F_ops [B,8,3,3], center [B,3]
//
// R13 = R12 resubmit (R12 failed at container level, never ran):
//  - reduce: X/mask tiles moved into smem via cp.async.bulk (TMA bulk copy,
//    no per-element LSU issue cost -- R10's 7.3us matched the 1.82cyc/LDG
//    LSU floor exactly). Compute reads smem at 48B-stride LDS.128
//    (conflict-free) with the exact R10 accumulation order (bit-identical).
//  - eig, project: unchanged from R10 (passing).
// ---------------------------------------------------------------------------

#define FA_MAXB 1024
__device__ double g_acc[FA_MAXB * 11];   // zero-initialized; restored to 0 each launch
__device__ float g_center[FA_MAXB * 3];
__device__ float g_V[FA_MAXB * 9];       // V[i][j] row-major (column j = eigvec j)

// ----------------------------- LAPACK helpers ------------------------------

__device__ __forceinline__ float f_sign(float a, float b) {
    float aa = fabsf(a);
    return (b >= 0.0f) ? aa : -aa;
}

__device__ __forceinline__ float slapy2f(float x, float y) {
    float ax = fabsf(x), ay = fabsf(y);
    float w = fmaxf(ax, ay), z = fminf(ax, ay);
    if (z == 0.0f) return w;
    float r = z / w;
    return w * sqrtf(1.0f + r * r);
}

// LAPACK >= 3.10 slartg convention: c >= 0, r = sign(f)*hypot, s = g/r.
__device__ __forceinline__ void slartgf(float f, float g, float& c, float& s, float& r) {
    if (g == 0.0f) {
        c = 1.0f; s = 0.0f; r = f;
    } else if (f == 0.0f) {
        c = 0.0f; s = (g >= 0.0f) ? 1.0f : -1.0f; r = fabsf(g);
    } else {
        float d = sqrtf(f * f + g * g);
        c = fabsf(f) / d;
        r = (f >= 0.0f) ? d : -d;
        s = g / r;
    }
}

__device__ void slaev2f(float a, float b, float c,
                        float& rt1, float& rt2, float& cs1, float& sn1) {
    float sm = a + c;
    float df = a - c;
    float adf = fabsf(df);
    float tb = b + b;
    float ab = fabsf(tb);
    float acmx, acmn;
    if (fabsf(a) > fabsf(c)) { acmx = a; acmn = c; } else { acmx = c; acmn = a; }
    float rt;
    if (adf > ab)      { float q = ab / adf;  rt = adf * sqrtf(1.0f + q * q); }
    else if (adf < ab) { float q = adf / ab;  rt = ab  * sqrtf(1.0f + q * q); }
    else               {                      rt = ab  * sqrtf(2.0f); }
    int sgn1;
    if (sm < 0.0f) {
        rt1 = 0.5f * (sm - rt); sgn1 = -1;
        rt2 = (acmx / rt1) * acmn - (b / rt1) * b;
    } else if (sm > 0.0f) {
        rt1 = 0.5f * (sm + rt); sgn1 = 1;
        rt2 = (acmx / rt1) * acmn - (b / rt1) * b;
    } else {
        rt1 = 0.5f * rt; rt2 = -0.5f * rt; sgn1 = 1;
    }
    float cs; int sgn2;
    if (df >= 0.0f) { cs = df + rt; sgn2 = 1; } else { cs = df - rt; sgn2 = -1; }
    float acs = fabsf(cs);
    if (acs > ab) {
        float ct = -tb / cs;
        sn1 = 1.0f / sqrtf(1.0f + ct * ct);
        cs1 = ct * sn1;
    } else {
        if (ab == 0.0f) { cs1 = 1.0f; sn1 = 0.0f; }
        else {
            float tn = -cs / tb;
            cs1 = 1.0f / sqrtf(1.0f + tn * tn);
            sn1 = tn * cs1;
        }
    }
    if (sgn1 == sgn2) { float tn = cs1; cs1 = -sn1; sn1 = tn; }
}

// ssteqr, COMPZ='I', n=3. d[3], e[2], z initialized to identity by the caller.
__device__ void ssteqr3(float d[3], float e[2], float z[3][3]) {
    const float eps = 5.9604645e-08f;          // slamch('E') for f32 = 2^-24
    const float eps2 = eps * eps;
    const float safmin = 1.1754943508222875e-38f;
    const int n = 3;
    const int nmaxit = n * 30;
    int jtot = 0;
    int l1 = 0;

    while (true) {
        if (l1 > n - 1) break;
        if (l1 > 0) e[l1 - 1] = 0.0f;
        int m = n - 1;
        for (int mm = l1; mm <= n - 2; mm++) {
            float tst = fabsf(e[mm]);
            if (tst == 0.0f) { m = mm; break; }
            if (tst <= (sqrtf(fabsf(d[mm])) * sqrtf(fabsf(d[mm + 1]))) * eps) {
                e[mm] = 0.0f; m = mm; break;
            }
        }
        int l = l1, lsv = l, lend = m, lendsv = lend;
        l1 = m + 1;
        if (lend == l) continue;
        if (fabsf(d[lend]) < fabsf(d[l])) { l = lendsv; lend = lsv; }

        if (lend > l) {
            // ---- QL iteration ----
            bool blockdone = false;
            while (!blockdone) {
                int m2 = lend;
                if (l != lend) {
                    for (int mm = l; mm <= lend - 1; mm++) {
                        float tst = e[mm] * e[mm];
                        if (tst <= (eps2 * fabsf(d[mm])) * fabsf(d[mm + 1]) + safmin) {
                            m2 = mm; break;
                        }
                    }
                }
                if (m2 < lend) e[m2] = 0.0f;
                float p = d[l];
                if (m2 == l) {
                    d[l] = p; l++;
                    if (l <= lend) continue;
                    blockdone = true; continue;
                }
                if (m2 == l + 1) {
                    float rt1, rt2, c, s;
                    slaev2f(d[l], e[l], d[l + 1], rt1, rt2, c, s);
                    for (int i = 0; i < 3; i++) {
                        float temp = z[i][l + 1];
                        z[i][l + 1] = c * temp - s * z[i][l];
                        z[i][l]     = s * temp + c * z[i][l];
                    }
                    d[l] = rt1; d[l + 1] = rt2; e[l] = 0.0f;
                    l += 2;
                    if (l <= lend) continue;
                    blockdone = true; continue;
                }
                if (jtot == nmaxit) { blockdone = true; continue; }
                jtot++;
                float g = (d[l + 1] - p) / (2.0f * e[l]);
                float r = slapy2f(g, 1.0f);
                g = d[m2] - p + e[l] / (g + f_sign(r, g));
                float s = 1.0f, c = 1.0f;
                p = 0.0f;
                float csv[2], snv[2];
                for (int i = m2 - 1; i >= l; i--) {
                    float f = s * e[i];
                    float b2 = c * e[i];
                    slartgf(g, f, c, s, r);
                    if (i != m2 - 1) e[i + 1] = r;
                    g = d[i + 1] - p;
                    r = (d[i] - g) * s + 2.0f * c * b2;
                    p = s * r;
                    d[i + 1] = g + p;
                    g = c * r - b2;
                    csv[i] = c; snv[i] = -s;
                }
                for (int j = m2 - 1; j >= l; j--) {        // slasr 'R','V','B'
                    float cj = csv[j], sj = snv[j];
                    for (int i = 0; i < 3; i++) {
                        float temp = z[i][j + 1];
                        z[i][j + 1] = cj * temp - sj * z[i][j];
                        z[i][j]     = sj * temp + cj * z[i][j];
                    }
                }
                d[l] = d[l] - p;
                e[l] = g;
            }
        } else {
            // ---- QR iteration ----
            bool blockdone = false;
            while (!blockdone) {
                int m2 = lend;
                if (l != lend) {
                    for (int mm = l; mm >= lend + 1; mm--) {
                        float tst = e[mm - 1] * e[mm - 1];
                        if (tst <= (eps2 * fabsf(d[mm])) * fabsf(d[mm - 1]) + safmin) {
                            m2 = mm; break;
                        }
                    }
                }
                if (m2 > lend) e[m2 - 1] = 0.0f;
                float p = d[l];
                if (m2 == l) {
                    d[l] = p; l--;
                    if (l >= lend) continue;
                    blockdone = true; continue;
                }
                if (m2 == l - 1) {
                    float rt1, rt2, c, s;
                    slaev2f(d[l - 1], e[l - 1], d[l], rt1, rt2, c, s);
                    for (int i = 0; i < 3; i++) {
                        float temp = z[i][l];
                        z[i][l]     = c * temp - s * z[i][l - 1];
                        z[i][l - 1] = s * temp + c * z[i][l - 1];
                    }
                    d[l - 1] = rt1; d[l] = rt2; e[l - 1] = 0.0f;
                    l -= 2;
                    if (l >= lend) continue;
                    blockdone = true; continue;
                }
                if (jtot == nmaxit) { blockdone = true; continue; }
                jtot++;
                float g = (d[l - 1] - p) / (2.0f * e[l - 1]);
                float r = slapy2f(g, 1.0f);
                g = d[m2] - p + e[l - 1] / (g + f_sign(r, g));
                float s = 1.0f, c = 1.0f;
                p = 0.0f;
                float csv[2], snv[2];
                for (int i = m2; i <= l - 1; i++) {
                    float f = s * e[i];
                    float b2 = c * e[i];
                    slartgf(g, f, c, s, r);
                    if (i != m2) e[i - 1] = r;
                    g = d[i] - p;
                    r = (d[i + 1] - g) * s + 2.0f * c * b2;
                    p = s * r;
                    d[i] = g + p;
                    g = c * r - b2;
                    csv[i] = c; snv[i] = s;
                }
                for (int j = m2; j <= l - 1; j++) {        // slasr 'R','V','F'
                    float cj = csv[j], sj = snv[j];
                    for (int i = 0; i < 3; i++) {
                        float temp = z[i][j + 1];
                        z[i][j + 1] = cj * temp - sj * z[i][j];
                        z[i][j]     = sj * temp + cj * z[i][j];
                    }
                }
                d[l] = d[l] - p;
                e[l - 1] = g;
            }
        }
    }
    // Selection sort ascending, swapping eigenvector columns (LAPACK label 160).
    for (int ii = 1; ii < n; ii++) {
        int i = ii - 1, k = i;
        float p = d[i];
        for (int j = ii; j < n; j++) if (d[j] < p) { k = j; p = d[j]; }
        if (k != i) {
            d[k] = d[i]; d[i] = p;
            for (int r2 = 0; r2 < 3; r2++) {
                float t = z[r2][i]; z[r2][i] = z[r2][k]; z[r2][k] = t;
            }
        }
    }
}

// ----------------------------- Kernel 1: reduce ----------------------------
// grid (ceil(N/1024), B), block 256. X/mask tiles arrive via cp.async.bulk
// (no per-element LSU cost); compute reads smem at 48B-stride LDS.128
// (conflict-free) in the exact R10 order (bit-identical sums).

__device__ __forceinline__ float warpRedF(float v) {
#pragma unroll
    for (int o = 16; o > 0; o >>= 1) v += __shfl_down_sync(0xffffffffu, v, o);
    return v;
}

__device__ __forceinline__ uint32_t fa_smem_u32(const void* p) {
    uint32_t a;
    asm("{ .reg .u64 t; cvta.to.shared.u64 t, %1; cvt.u32.u64 %0, t; }"
        : "=r"(a) : "l"(p));
    return a;
}

__global__ void __launch_bounds__(256)
fa_reduce_kernel(const float* __restrict__ X,
                 const float* __restrict__ mask, int N) {
    __shared__ float4 sX[768];                  // 1024 pts * 3 f = 12 KB
    __shared__ float4 sM[256];                  // 1024 pts * 1 f = 4 KB
    __shared__ unsigned long long mbar;
    __shared__ float sred[8][11];

    int b = blockIdx.y;
    int tid = threadIdx.x;
    int tile0 = blockIdx.x * 1024;              // first point of tile
    int pts = min(1024, N - tile0);             // N % 4 == 0 -> pts % 4 == 0
    unsigned xbytes = (unsigned)pts * 12u;      // multiple of 48 -> 16B ok
    unsigned mbytes = (unsigned)pts * 4u;       // multiple of 16

    uint32_t mb = fa_smem_u32(&mbar);
    if (tid == 0) {
        asm volatile("mbarrier.init.shared.b64 [%0], %1;"
                     :: "r"(mb), "r"(1u) : "memory");
    }
    __syncthreads();
    if (tid == 0) {
        asm volatile("mbarrier.arrive.expect_tx.shared.b64 _, [%0], %1;"
                     :: "r"(mb), "r"(xbytes + mbytes) : "memory");
        const float* xsrc = X + (size_t)b * N * 3 + (size_t)tile0 * 3;
        const float* msrc = mask + (size_t)b * N + tile0;
        asm volatile(
            "cp.async.bulk.shared::cta.global.mbarrier::complete_tx::bytes "
            "[%0], [%1], %2, [%3];"
            :: "r"(fa_smem_u32(sX)), "l"(xsrc), "r"(xbytes), "r"(mb) : "memory");
        asm volatile(
            "cp.async.bulk.shared::cta.global.mbarrier::complete_tx::bytes "
            "[%0], [%1], %2, [%3];"
            :: "r"(fa_smem_u32(sM)), "l"(msrc), "r"(mbytes), "r"(mb) : "memory");
    }
    // All threads wait for phase 0 completion (acquire).
    {
        uint32_t done;
        asm volatile(
            "{\n\t"
            ".reg .pred p;\n\t"
            "WAIT_%=: mbarrier.try_wait.parity.acquire.cta.shared::cta.b64 p, [%1], %2, 0x989680;\n\t"
            "selp.b32 %0, 1, 0, p;\n\t"
            "@!p bra.uni WAIT_%=;\n\t"
            "}"
            : "=r"(done) : "r"(mb), "r"(0u) : "memory");
        (void)done;
    }

    // Compute: identical accumulation order to R10 (thread owns 4 points).
    float4 m4 = {}, fa = {}, fb = {}, fc = {};
    if (tid * 4 < pts) {
        fa = sX[tid * 3 + 0];
        fb = sX[tid * 3 + 1];
        fc = sX[tid * 3 + 2];
        m4 = sM[tid];
    }

    float acc[11];
#pragma unroll
    for (int k = 0; k < 11; k++) acc[k] = 0.0f;
    // acc: 0 sm, 1 sm2, 2..4 s1xyz, 5 xx, 6 xy, 7 xz, 8 yy, 9 yz, 10 zz
    {
        float px[4] = {fa.x, fa.w, fb.z, fc.y};
        float py[4] = {fa.y, fb.x, fb.w, fc.z};
        float pz[4] = {fa.z, fb.y, fc.x, fc.w};
        float mm[4] = {m4.x, m4.y, m4.z, m4.w};
#pragma unroll
        for (int k = 0; k < 4; k++) {
            float x = px[k], y = py[k], z = pz[k], m = mm[k];
            acc[0] += m;         acc[1] = fmaf(m, m, acc[1]);
            acc[2] = fmaf(m, x, acc[2]);
            acc[3] = fmaf(m, y, acc[3]);
            acc[4] = fmaf(m, z, acc[4]);
            acc[5] = fmaf(x, x, acc[5]);
            acc[6] = fmaf(x, y, acc[6]);
            acc[7] = fmaf(x, z, acc[7]);
            acc[8] = fmaf(y, y, acc[8]);
            acc[9] = fmaf(y, z, acc[9]);
            acc[10] = fmaf(z, z, acc[10]);
        }
    }

    int lane = tid & 31, w = tid >> 5;
#pragma unroll
    for (int k = 0; k < 11; k++) {
        float v = warpRedF(acc[k]);
        if (lane == 0) sred[w][k] = v;
    }
    __syncthreads();
    if (tid < 11) {
        double v = 0.0;
#pragma unroll
        for (int ww = 0; ww < 8; ww++) v += (double)sred[ww][tid];
        atomicAdd(&g_acc[b * 11 + tid], v);
    }
}

// ------------------- Kernel 2: finalize + eigh + F_ops ----------------------
// One matrix per CTA (lane 0 only) -> no warp divergence in ssteqr emulation.

__global__ void __launch_bounds__(32)
fa_eig_kernel(float* __restrict__ outF, float* __restrict__ outC, int B) {
    int b = blockIdx.x;
    if (threadIdx.x != 0 || b >= B) return;

    double t[11];
#pragma unroll
    for (int k = 0; k < 11; k++) {
        t[k] = g_acc[b * 11 + k];
        g_acc[b * 11 + k] = 0.0;      // restore zero state for next launch
    }
    double sm = t[0], sm2 = t[1];
    double s1x = t[2], s1y = t[3], s1z = t[4];
    // f32 center exactly as reference computes (f32 divide)
    float cfx = (float)s1x / (float)sm;
    float cfy = (float)s1y / (float)sm;
    float cfz = (float)s1z / (float)sm;
    g_center[b * 3 + 0] = cfx;
    g_center[b * 3 + 1] = cfy;
    g_center[b * 3 + 2] = cfz;
    // C_ij = Sxx_ij - c_i*S1_j - c_j*S1_i + c_i*c_j*Sm2 (double expansion)
    double cx = s1x / sm, cy = s1y / sm, cz = s1z / sm;
    float a11 = (float)(t[5]  - 2.0 * cx * s1x + cx * cx * sm2);
    float a21 = (float)(t[6]  - cx * s1y - cy * s1x + cx * cy * sm2);
    float a31 = (float)(t[7]  - cx * s1z - cz * s1x + cx * cz * sm2);
    float a22 = (float)(t[8]  - 2.0 * cy * s1y + cy * cy * sm2);
    float a32 = (float)(t[9]  - cy * s1z - cz * s1y + cy * cz * sm2);
    float a33 = (float)(t[10] - 2.0 * cz * s1z + cz * cz * sm2);

    // ---- ssytd2 (lower, n=3): one Householder reflector ----
    float d[3], e[2];
    float tau = 0.0f, v2 = 0.0f;
    {
        float alpha = a21;
        float xnorm = fabsf(a31);
        if (xnorm == 0.0f) {
            tau = 0.0f; v2 = 0.0f;
            e[0] = alpha;
            d[0] = a11; d[1] = a22; d[2] = a33;
            e[1] = a32;
        } else {
            float beta = -f_sign(slapy2f(alpha, xnorm), alpha);
            tau = (beta - alpha) / beta;
            v2 = a31 * (1.0f / (alpha - beta));
            e[0] = beta;
            float w1 = tau * (a22 + a32 * v2);
            float w2 = tau * (a32 + a33 * v2);
            float alpha2 = -0.5f * tau * (w1 + w2 * v2);
            w1 += alpha2;
            w2 += alpha2 * v2;
            d[0] = a11;
            d[1] = a22 - 2.0f * w1;
            e[1] = a32 - (v2 * w1 + w2);
            d[2] = a33 - 2.0f * v2 * w2;
        }
    }

    float z[3][3] = {{1.f, 0.f, 0.f}, {0.f, 1.f, 0.f}, {0.f, 0.f, 1.f}};
    ssteqr3(d, e, z);

    // ---- sormtr: V = H1 * Z, H1 = I - tau*u*u^T, u = (0, 1, v2) ----
    float V[3][3];
#pragma unroll
    for (int j = 0; j < 3; j++) {
        float tt = tau * (z[1][j] + v2 * z[2][j]);
        V[0][j] = z[0][j];
        V[1][j] = z[1][j] - tt;
        V[2][j] = z[2][j] - v2 * tt;
    }
#pragma unroll
    for (int i = 0; i < 3; i++)
#pragma unroll
        for (int j = 0; j < 3; j++)
            g_V[b * 9 + i * 3 + j] = V[i][j];

    // F_ops[b,o,i,j] = OPS[o][j] * V[i][j]; OPS[o] = (o&4?+1:-1, o&2?+1:-1, o&1?+1:-1)
    for (int o = 0; o < 8; o++) {
        float sg[3] = {(o & 4) ? 1.f : -1.f, (o & 2) ? 1.f : -1.f, (o & 1) ? 1.f : -1.f};
#pragma unroll
        for (int i = 0; i < 3; i++)
#pragma unroll
            for (int j = 0; j < 3; j++)
                outF[(((size_t)b * 8 + o) * 3 + i) * 3 + j] = sg[j] * V[i][j];
    }
    outC[b * 3 + 0] = cfx;
    outC[b * 3 + 1] = cfy;
    outC[b * 3 + 2] = cfz;
}

// ------------------------- Kernel 3: projection (h) -------------------------
// Block = 256 threads = 1024-point tile. Stage y in smem, then write each op
// row with lane-contiguous float4 stores; signs applied by XOR of sign bit.

__global__ void __launch_bounds__(256)
fa_project_kernel(const float* __restrict__ X,
                  const float* __restrict__ mask,
                  float* __restrict__ outh, int N) {
    int b = blockIdx.y;
    __shared__ float4 sy4[768];          // 1024 points * 3 floats = 3072 f = 768 f4
    __shared__ float sV[9];
    __shared__ float sc[3];
    if (threadIdx.x < 9) sV[threadIdx.x] = g_V[b * 9 + threadIdx.x];
    if (threadIdx.x < 3) sc[threadIdx.x] = g_center[b * 3 + threadIdx.x];
    __syncthreads();

    int tid = threadIdx.x;
    int nq = N >> 2;                      // float4-groups per batch row
    int g = blockIdx.x * blockDim.x + tid;  // this thread's group (4 points)
    bool valid = g < nq;

    const float4* Xb = reinterpret_cast<const float4*>(X + (size_t)b * N * 3);
    const float4* Mb = reinterpret_cast<const float4*>(mask + (size_t)b * N);

    if (valid) {
        float4 fa = Xb[g * 3 + 0];
        float4 fb = Xb[g * 3 + 1];
        float4 fc = Xb[g * 3 + 2];
        float4 m4 = Mb[g];

        float cx = sc[0], cy = sc[1], cz = sc[2];
        float v0 = sV[0], v1 = sV[1], v2 = sV[2];
        float v3 = sV[3], v4 = sV[4], v5 = sV[5];
        float v6 = sV[6], v7 = sV[7], v8 = sV[8];

        float px[4] = {fa.x, fa.w, fb.z, fc.y};
        float py[4] = {fa.y, fb.x, fb.w, fc.z};
        float pz[4] = {fa.z, fb.y, fc.x, fc.w};
        float mm[4] = {m4.x, m4.y, m4.z, m4.w};

        float yv[12];
#pragma unroll
        for (int k = 0; k < 4; k++) {
            float xcx = px[k] - cx * mm[k];
            float xcy = py[k] - cy * mm[k];
            float xcz = pz[k] - cz * mm[k];
            // y_i = sum_j V[j][i] * xc_j (projection onto eigenvector i)
            yv[k * 3 + 0] = v0 * xcx + v3 * xcy + v6 * xcz;
            yv[k * 3 + 1] = v1 * xcx + v4 * xcy + v7 * xcz;
            yv[k * 3 + 2] = v2 * xcx + v5 * xcy + v8 * xcz;
        }
        sy4[tid * 3 + 0] = make_float4(yv[0], yv[1], yv[2],  yv[3]);
        sy4[tid * 3 + 1] = make_float4(yv[4], yv[5], yv[6],  yv[7]);
        sy4[tid * 3 + 2] = make_float4(yv[8], yv[9], yv[10], yv[11]);
    }
    __syncthreads();

    // Tile covers points [tile0, tile0 + 1024); floats [tile0*3, +3072).
    int tile0 = blockIdx.x * blockDim.x * 4;           // first point of tile
    int tile_pts = min(N - tile0, (int)blockDim.x * 4);
    int tile_f4 = (tile_pts * 3) >> 2;                 // float4 count in tile

    // Read this thread's 3 unsigned float4s once; reuse across all 8 ops.
    // Precompute idx%3 per chunk (idx = tid + c*256; 256 % 3 == 1 -> m rotates).
    uint4 u[3];
    int mmod[3];
    int mt = tid % 3;
#pragma unroll
    for (int c = 0; c < 3; c++) {
        int idx = tid + c * 256;
        mmod[c] = mt;
        mt = (mt == 2) ? 0 : mt + 1;     // (tid + 256) % 3 advances by 1
        if (idx < tile_f4) {
            float4 v = sy4[idx];
            u[c] = make_uint4(__float_as_uint(v.x), __float_as_uint(v.y),
                              __float_as_uint(v.z), __float_as_uint(v.w));
        }
    }

    size_t rowstride = (size_t)N * 3;
    float* obase = outh + ((size_t)b * 8) * rowstride + (size_t)tile0 * 3;

#pragma unroll
    for (int o = 0; o < 8; o++) {
        // component sign masks: +1 -> 0, -1 -> 0x80000000
        unsigned s0 = (o & 4) ? 0u : 0x80000000u;
        unsigned s1 = (o & 2) ? 0u : 0x80000000u;
        unsigned s2 = (o & 1) ? 0u : 0x80000000u;
        // sign-vector for a float4 starting at float offset f (by f mod 3)
        uint4 sm0 = make_uint4(s0, s1, s2, s0);
        uint4 sm1 = make_uint4(s1, s2, s0, s1);
        uint4 sm2 = make_uint4(s2, s0, s1, s2);
        uint4* orow = reinterpret_cast<uint4*>(obase + (size_t)o * rowstride);
#pragma unroll
        for (int c = 0; c < 3; c++) {
            int idx = tid + c * 256;
            if (idx < tile_f4) {
                int m = mmod[c];
                uint4 sv = (m == 0) ? sm0 : (m == 1) ? sm1 : sm2;
                uint4 w = make_uint4(u[c].x ^ sv.x, u[c].y ^ sv.y,
                                     u[c].z ^ sv.z, u[c].w ^ sv.w);
                __stcs(orow + idx, w);
            }
        }
    }
}

// ------------------------------- launch ------------------------------------

extern "C" void kernel_launch(void* const* d_in, const int* in_sizes, int n_in,
                              void* d_out, int out_size) {
    const float* X = (const float*)d_in[0];
    const float* mask = (const float*)d_in[1];
    float* out = (float*)d_out;

    long long BN = in_sizes[1];                       // B*N
    long long B = ((long long)out_size - 24LL * BN) / 75LL;
    if (B < 1) B = 1;
    int N = (int)(BN / B);

    float* outF = out + 24LL * BN;                    // F_ops after h
    float* outC = outF + 72LL * B;                    // center after F_ops

    int Sr = (N + 1023) / 1024;                       // 1024 points per CTA
    if (Sr < 1) Sr = 1;
    dim3 rgrid((unsigned)Sr, (unsigned)B);
    fa_reduce_kernel<<<rgrid, 256>>>(X, mask, N);
    fa_eig_kernel<<<(int)B, 32>>>(outF, outC, (int)B);
    int nq = N / 4;
    dim3 pgrid((unsigned)((nq + 255) / 256), (unsigned)B);
    fa_project_kernel<<<pgrid, 256>>>(X, mask, out, N);
}